// round 2
// baseline (speedup 1.0000x reference)
#include <cuda_runtime.h>
#include <math.h>

// Problem constants
#define BATCH 16
#define CCH   512
#define TT    1024
#define NHEAD 8
#define DH    64
#define NGRP  32
#define CPG   16   // channels per group

// Scratch (device globals: allocation-free per harness rules)
__device__ float g_xn  [(size_t)BATCH * CCH * TT];        // 32 MB
__device__ float g_qkv [(size_t)BATCH * 3 * CCH * TT];    // 96 MB
__device__ float g_attn[(size_t)BATCH * CCH * TT];        // 32 MB

// ---------------------------------------------------------------------------
// GroupNorm: one block per (batch, group). 16 channels x 1024 t = 16384 elems.
// ---------------------------------------------------------------------------
__global__ __launch_bounds__(256) void gn_kernel(
    const float* __restrict__ x, const float* __restrict__ sc,
    const float* __restrict__ bi, float* __restrict__ xn)
{
    int b = blockIdx.x >> 5;
    int g = blockIdx.x & 31;
    const float4* xp = (const float4*)(x + ((size_t)b * CCH + g * CPG) * TT);
    float4* op = (float4*)(xn + ((size_t)b * CCH + g * CPG) * TT);
    int tid = threadIdx.x;

    float s = 0.f, s2 = 0.f;
    #pragma unroll 4
    for (int i = tid; i < CPG * TT / 4; i += 256) {
        float4 v = xp[i];
        s  += v.x + v.y + v.z + v.w;
        s2 += v.x * v.x + v.y * v.y + v.z * v.z + v.w * v.w;
    }
    __shared__ float red[512];
    red[tid] = s; red[256 + tid] = s2;
    __syncthreads();
    for (int st = 128; st > 0; st >>= 1) {
        if (tid < st) {
            red[tid] += red[tid + st];
            red[256 + tid] += red[256 + tid + st];
        }
        __syncthreads();
    }
    float mean = red[0] * (1.f / (CPG * TT));
    float var  = red[256] * (1.f / (CPG * TT)) - mean * mean;
    float rinv = rsqrtf(var + 1e-5f);

    #pragma unroll 4
    for (int i = tid; i < CPG * TT / 4; i += 256) {
        int cl = i >> 8;                  // 256 float4 per channel row
        float scale = sc[g * CPG + cl] * rinv;
        float bias  = bi[g * CPG + cl];
        float4 v = xp[i];
        float4 o;
        o.x = (v.x - mean) * scale + bias;
        o.y = (v.y - mean) * scale + bias;
        o.z = (v.z - mean) * scale + bias;
        o.w = (v.w - mean) * scale + bias;
        op[i] = o;
    }
}

// ---------------------------------------------------------------------------
// Batched GEMM: out[b][m][n] = sum_k W[m][k] * X[b][k][n] + bias[m] (+res)
// Block tile 64x64, K-chunks of 16, 256 threads, 4x4 micro-tile.
// ---------------------------------------------------------------------------
template <bool RES>
__global__ __launch_bounds__(256) void gemm_kernel(
    const float* __restrict__ W, const float* __restrict__ X,
    const float* __restrict__ bias, const float* __restrict__ res,
    float* __restrict__ out, int M, int K, int N)
{
    __shared__ float sW[16 * 64];
    __shared__ float sX[16 * 64];
    int b  = blockIdx.z;
    int m0 = blockIdx.y * 64;
    int n0 = blockIdx.x * 64;
    int tid = threadIdx.x;
    int tx = tid & 15, ty = tid >> 4;
    const float* Xb = X + (size_t)b * K * N;

    float acc[4][4] = {};
    int wm = tid >> 2;
    int wk = (tid & 3) << 2;
    int xk = tid >> 4;
    int xn = (tid & 15) << 2;

    for (int k0 = 0; k0 < K; k0 += 16) {
        float4 w4 = *(const float4*)(W + (size_t)(m0 + wm) * K + k0 + wk);
        float4 x4 = *(const float4*)(Xb + (size_t)(k0 + xk) * N + n0 + xn);
        __syncthreads();
        sW[(wk + 0) * 64 + wm] = w4.x;
        sW[(wk + 1) * 64 + wm] = w4.y;
        sW[(wk + 2) * 64 + wm] = w4.z;
        sW[(wk + 3) * 64 + wm] = w4.w;
        *(float4*)&sX[xk * 64 + xn] = x4;
        __syncthreads();
        #pragma unroll
        for (int kk = 0; kk < 16; kk++) {
            float4 a4 = *(const float4*)&sW[kk * 64 + (ty << 2)];
            float4 b4 = *(const float4*)&sX[kk * 64 + (tx << 2)];
            float av[4] = {a4.x, a4.y, a4.z, a4.w};
            float bv[4] = {b4.x, b4.y, b4.z, b4.w};
            #pragma unroll
            for (int i = 0; i < 4; i++)
                #pragma unroll
                for (int j = 0; j < 4; j++)
                    acc[i][j] += av[i] * bv[j];
        }
    }

    #pragma unroll
    for (int i = 0; i < 4; i++) {
        int m = m0 + (ty << 2) + i;
        float bv = bias[m];
        float* orow = out + ((size_t)b * M + m) * N + n0 + (tx << 2);
        float4 o;
        o.x = acc[i][0] + bv; o.y = acc[i][1] + bv;
        o.z = acc[i][2] + bv; o.w = acc[i][3] + bv;
        if (RES) {
            const float4 r = *(const float4*)(res + ((size_t)b * M + m) * N + n0 + (tx << 2));
            o.x += r.x; o.y += r.y; o.z += r.z; o.w += r.w;
        }
        *(float4*)orow = o;
    }
}

// ---------------------------------------------------------------------------
// Flash attention (fp32). One block per (head, q-tile of 64). 256 threads.
// q/k/v layout: (dh=64 rows, t=1024 cols) inside g_qkv (b,1536,t),
// head h of batch b at row offset h*192 (+0 q, +64 k, +128 v).
// Shared: sQ[64][64], sK[64][64], sP[64][64], sV[64][68]  = 66560 B dynamic.
// ---------------------------------------------------------------------------
#define ATTN_SMEM_FLOATS (4096 + 4096 + 4096 + 64 * 68)
#define ATTN_SMEM_BYTES  (ATTN_SMEM_FLOATS * 4)

__global__ __launch_bounds__(256) void attn_kernel(
    const float* __restrict__ qkv, float* __restrict__ attn_out)
{
    extern __shared__ float sm[];
    float* sQ = sm;                 // [64][64] : [d][qi]
    float* sK = sm + 4096;          // [64][64] : [d][ki]
    float* sP = sm + 8192;          // [64][64] : [qi][ki]
    float* sV = sm + 12288;         // [64][68] : [d][ki] (pad 4)

    int hb = blockIdx.y;            // b*8 + h
    int b = hb >> 3, h = hb & 7;
    int q0 = blockIdx.x * 64;
    const float* base = qkv + ((size_t)b * (3 * CCH) + h * 3 * DH) * TT;
    const float* Qp = base;
    const float* Kp = base + (size_t)DH * TT;
    const float* Vp = base + (size_t)2 * DH * TT;

    int tid = threadIdx.x;
    int tx = tid & 15, ty = tid >> 4;

    // Load Q tile once: sQ[d][qi]
    for (int i = tid; i < 1024; i += 256) {
        int d = i >> 4, q4 = (i & 15) << 2;
        *(float4*)&sQ[d * 64 + q4] = *(const float4*)(Qp + (size_t)d * TT + q0 + q4);
    }

    float m_run[4], l_run[4], O[4][4];
    #pragma unroll
    for (int i = 0; i < 4; i++) {
        m_run[i] = -INFINITY; l_run[i] = 0.f;
        #pragma unroll
        for (int j = 0; j < 4; j++) O[i][j] = 0.f;
    }

    for (int kt = 0; kt < TT / 64; kt++) {
        int k0 = kt * 64;
        __syncthreads();   // previous iteration's GEMM2 done (and Q stores on kt=0)
        for (int i = tid; i < 1024; i += 256) {
            int d = i >> 4, k4 = (i & 15) << 2;
            *(float4*)&sK[d * 64 + k4] = *(const float4*)(Kp + (size_t)d * TT + k0 + k4);
            *(float4*)&sV[d * 68 + k4] = *(const float4*)(Vp + (size_t)d * TT + k0 + k4);
        }
        __syncthreads();

        // S = (Q^T K) * 1/sqrt(dh)
        float S[4][4] = {};
        #pragma unroll 8
        for (int d = 0; d < 64; d++) {
            float4 a4 = *(const float4*)&sQ[d * 64 + (ty << 2)];
            float4 b4 = *(const float4*)&sK[d * 64 + (tx << 2)];
            float av[4] = {a4.x, a4.y, a4.z, a4.w};
            float bv[4] = {b4.x, b4.y, b4.z, b4.w};
            #pragma unroll
            for (int i = 0; i < 4; i++)
                #pragma unroll
                for (int j = 0; j < 4; j++)
                    S[i][j] += av[i] * bv[j];
        }

        // Online softmax per q-row (rows owned by the 16 tx-lanes jointly)
        #pragma unroll
        for (int i = 0; i < 4; i++) {
            float mx = fmaxf(fmaxf(S[i][0], S[i][1]), fmaxf(S[i][2], S[i][3])) * 0.125f;
            #pragma unroll
            for (int o = 8; o > 0; o >>= 1)
                mx = fmaxf(mx, __shfl_xor_sync(0xffffffffu, mx, o, 16));
            float mnew = fmaxf(m_run[i], mx);
            float alpha = __expf(m_run[i] - mnew);
            m_run[i] = mnew;
            float rs = 0.f;
            #pragma unroll
            for (int j = 0; j < 4; j++) {
                S[i][j] = __expf(S[i][j] * 0.125f - mnew);
                rs += S[i][j];
            }
            #pragma unroll
            for (int o = 8; o > 0; o >>= 1)
                rs += __shfl_xor_sync(0xffffffffu, rs, o, 16);
            l_run[i] = l_run[i] * alpha + rs;
            #pragma unroll
            for (int j = 0; j < 4; j++) O[i][j] *= alpha;
        }

        // Write P
        #pragma unroll
        for (int i = 0; i < 4; i++)
            *(float4*)&sP[((ty << 2) + i) * 64 + (tx << 2)] =
                make_float4(S[i][0], S[i][1], S[i][2], S[i][3]);
        __syncthreads();

        // O(qi, d) += sum_ki P(qi,ki) V(d,ki)
        #pragma unroll 4
        for (int k4 = 0; k4 < 64; k4 += 4) {
            float4 p[4], v[4];
            #pragma unroll
            for (int i = 0; i < 4; i++)
                p[i] = *(const float4*)&sP[((ty << 2) + i) * 64 + k4];
            #pragma unroll
            for (int j = 0; j < 4; j++)
                v[j] = *(const float4*)&sV[((tx << 2) + j) * 68 + k4];
            #pragma unroll
            for (int i = 0; i < 4; i++)
                #pragma unroll
                for (int j = 0; j < 4; j++)
                    O[i][j] += p[i].x * v[j].x + p[i].y * v[j].y
                             + p[i].z * v[j].z + p[i].w * v[j].w;
        }
    }

    float rl[4];
    #pragma unroll
    for (int i = 0; i < 4; i++) rl[i] = 1.f / l_run[i];

    // attn_out layout (b, 512, t): row = h*64 + d, col = q0 + qi
    #pragma unroll
    for (int j = 0; j < 4; j++) {
        int d = (tx << 2) + j;
        float4 o4 = make_float4(O[0][j] * rl[0], O[1][j] * rl[1],
                                O[2][j] * rl[2], O[3][j] * rl[3]);
        *(float4*)&attn_out[((size_t)b * CCH + h * DH + d) * TT + q0 + (ty << 2)] = o4;
    }
}

// ---------------------------------------------------------------------------
extern "C" void kernel_launch(void* const* d_in, const int* in_sizes, int n_in,
                              void* d_out, int out_size)
{
    const float* x     = (const float*)d_in[0];
    const float* gsc   = (const float*)d_in[1];
    const float* gbi   = (const float*)d_in[2];
    const float* wqkv  = (const float*)d_in[3];
    const float* bqkv  = (const float*)d_in[4];
    const float* wproj = (const float*)d_in[5];
    const float* bproj = (const float*)d_in[6];
    float* out = (float*)d_out;

    float *xn, *qkv, *attn;
    cudaGetSymbolAddress((void**)&xn,   g_xn);
    cudaGetSymbolAddress((void**)&qkv,  g_qkv);
    cudaGetSymbolAddress((void**)&attn, g_attn);

    cudaFuncSetAttribute(attn_kernel,
                         cudaFuncAttributeMaxDynamicSharedMemorySize,
                         ATTN_SMEM_BYTES);

    gn_kernel<<<BATCH * NGRP, 256>>>(x, gsc, gbi, xn);

    // QKV: M=1536, K=512, N=1024, per batch
    gemm_kernel<false><<<dim3(TT / 64, (3 * CCH) / 64, BATCH), 256>>>(
        wqkv, xn, bqkv, nullptr, qkv, 3 * CCH, CCH, TT);

    attn_kernel<<<dim3(TT / 64, BATCH * NHEAD), 256, ATTN_SMEM_BYTES>>>(qkv, attn);

    // Proj + residual: M=512, K=512, N=1024
    gemm_kernel<true><<<dim3(TT / 64, CCH / 64, BATCH), 256>>>(
        wproj, attn, bproj, x, out, CCH, CCH, TT);
}

// round 6
// speedup vs baseline: 1.3548x; 1.3548x over previous
#include <cuda_runtime.h>
#include <math.h>
#include <cstdint>

// Problem constants
#define BATCH 16
#define CCH   512
#define TT    1024
#define NHEAD 8
#define DH    64
#define NGRP  32
#define CPG   16

// Scratch (device globals: allocation-free per harness rules)
__device__ float g_xn  [(size_t)BATCH * CCH * TT];        // 32 MB
__device__ float g_qkv [(size_t)BATCH * 3 * CCH * TT];    // 96 MB
__device__ float g_attn[(size_t)BATCH * CCH * TT];        // 32 MB

__device__ __forceinline__ uint32_t f2tf32(float f) {
    uint32_t r;
    asm("cvt.rna.tf32.f32 %0, %1;" : "=r"(r) : "f"(f));
    return r;
}

__device__ __forceinline__ void mma_tf32(
    float d[4], const uint32_t a[4], const uint32_t bfr[2])
{
    asm volatile(
        "mma.sync.aligned.m16n8k8.row.col.f32.tf32.tf32.f32 "
        "{%0,%1,%2,%3}, {%4,%5,%6,%7}, {%8,%9}, {%0,%1,%2,%3};"
        : "+f"(d[0]), "+f"(d[1]), "+f"(d[2]), "+f"(d[3])
        : "r"(a[0]), "r"(a[1]), "r"(a[2]), "r"(a[3]),
          "r"(bfr[0]), "r"(bfr[1]));
}

// ---------------------------------------------------------------------------
// GroupNorm (unchanged)
// ---------------------------------------------------------------------------
__global__ __launch_bounds__(256) void gn_kernel(
    const float* __restrict__ x, const float* __restrict__ sc,
    const float* __restrict__ bi, float* __restrict__ xn)
{
    int b = blockIdx.x >> 5;
    int g = blockIdx.x & 31;
    const float4* xp = (const float4*)(x + ((size_t)b * CCH + g * CPG) * TT);
    float4* op = (float4*)(xn + ((size_t)b * CCH + g * CPG) * TT);
    int tid = threadIdx.x;

    float s = 0.f, s2 = 0.f;
    #pragma unroll 4
    for (int i = tid; i < CPG * TT / 4; i += 256) {
        float4 v = xp[i];
        s  += v.x + v.y + v.z + v.w;
        s2 += v.x * v.x + v.y * v.y + v.z * v.z + v.w * v.w;
    }
    __shared__ float red[512];
    red[tid] = s; red[256 + tid] = s2;
    __syncthreads();
    for (int st = 128; st > 0; st >>= 1) {
        if (tid < st) {
            red[tid] += red[tid + st];
            red[256 + tid] += red[256 + tid + st];
        }
        __syncthreads();
    }
    float mean = red[0] * (1.f / (CPG * TT));
    float var  = red[256] * (1.f / (CPG * TT)) - mean * mean;
    float rinv = rsqrtf(var + 1e-5f);

    #pragma unroll 4
    for (int i = tid; i < CPG * TT / 4; i += 256) {
        int cl = i >> 8;
        float scale = sc[g * CPG + cl] * rinv;
        float bias  = bi[g * CPG + cl];
        float4 v = xp[i];
        float4 o;
        o.x = (v.x - mean) * scale + bias;
        o.y = (v.y - mean) * scale + bias;
        o.z = (v.z - mean) * scale + bias;
        o.w = (v.w - mean) * scale + bias;
        op[i] = o;
    }
}

// ---------------------------------------------------------------------------
// tf32 mma.sync GEMM: out[b][m][n] = sum_k W[m][k]*X[b][k][n] + bias[m] (+res)
// Block tile 128x128, 8 warps (warp tile 64x32), K-chunk 16, double-buffered.
// SMEM: A[128][20] (pad: banks (4g+c)%32 distinct), B[16][136] ((8k+n)%32).
// ---------------------------------------------------------------------------
#define SA_STRIDE 20
#define SB_STRIDE 136
#define SA_FLOATS (128 * SA_STRIDE)          // 2560
#define SB_FLOATS (16 * SB_STRIDE)           // 2176
#define GEMM_SMEM_FLOATS (2 * SA_FLOATS + 2 * SB_FLOATS)
#define GEMM_SMEM_BYTES  (GEMM_SMEM_FLOATS * 4)   // 37888

template <bool RES>
__global__ __launch_bounds__(256, 2) void gemm_mma(
    const float* __restrict__ W, const float* __restrict__ X,
    const float* __restrict__ bias, const float* __restrict__ res,
    float* __restrict__ out, int M, int K, int N)
{
    extern __shared__ uint32_t smem[];

    int b  = blockIdx.z;
    int m0 = blockIdx.y * 128;
    int n0 = blockIdx.x * 128;
    int tid = threadIdx.x;
    int wid = tid >> 5, lane = tid & 31;
    int g = lane >> 2, tg = lane & 3;          // groupID, threadInGroup
    int warp_m = wid & 1, warp_n = wid >> 1;   // 2 x 4
    int mwb = warp_m * 64;                     // warp m base (in tile)
    int nwb = warp_n * 32;                     // warp n base (in tile)
    const float* Xb = X + (size_t)b * K * N;

    float acc[4][4][4];
    #pragma unroll
    for (int mt = 0; mt < 4; mt++)
        #pragma unroll
        for (int nt = 0; nt < 4; nt++)
            #pragma unroll
            for (int r = 0; r < 4; r++) acc[mt][nt][r] = 0.f;

    // gmem load indices (per-thread, fixed)
    int a_row = tid >> 2, a_c4 = (tid & 3) * 4;          // A: 128x16 -> 2 float4/thr? no: 512 f4, 256 thr -> 2
    int b_row = tid >> 5, b_c4 = (tid & 31) * 4;

    float4 pa[2], pb[2];
    // prefetch chunk 0
    {
        const float* Wp = W + (size_t)(m0 + a_row) * K;
        pa[0] = *(const float4*)(Wp + a_c4);
        pa[1] = *(const float4*)(Wp + 64 * K + a_c4);     // rows a_row and a_row+64
        const float* Xp = Xb + (size_t)b_row * N + n0 + b_c4;
        pb[0] = *(const float4*)(Xp);
        pb[1] = *(const float4*)(Xp + 8 * N);             // k rows b_row, b_row+8
    }

    const int nchunks = K / 16;
    for (int c = 0; c < nchunks; c++) {
        int buf = c & 1;
        uint32_t* sA = smem + buf * SA_FLOATS;
        uint32_t* sB = smem + 2 * SA_FLOATS + buf * SB_FLOATS;

        // store prefetched chunk (tf32-converted)
        {
            uint32_t* p0 = sA + a_row * SA_STRIDE + a_c4;
            p0[0] = f2tf32(pa[0].x); p0[1] = f2tf32(pa[0].y);
            p0[2] = f2tf32(pa[0].z); p0[3] = f2tf32(pa[0].w);
            uint32_t* p1 = sA + (a_row + 64) * SA_STRIDE + a_c4;
            p1[0] = f2tf32(pa[1].x); p1[1] = f2tf32(pa[1].y);
            p1[2] = f2tf32(pa[1].z); p1[3] = f2tf32(pa[1].w);
            uint32_t* q0 = sB + b_row * SB_STRIDE + b_c4;
            q0[0] = f2tf32(pb[0].x); q0[1] = f2tf32(pb[0].y);
            q0[2] = f2tf32(pb[0].z); q0[3] = f2tf32(pb[0].w);
            uint32_t* q1 = sB + (b_row + 8) * SB_STRIDE + b_c4;
            q1[0] = f2tf32(pb[1].x); q1[1] = f2tf32(pb[1].y);
            q1[2] = f2tf32(pb[1].z); q1[3] = f2tf32(pb[1].w);
        }
        __syncthreads();

        // prefetch next chunk (overlaps with compute below)
        if (c + 1 < nchunks) {
            int k0 = (c + 1) * 16;
            const float* Wp = W + (size_t)(m0 + a_row) * K + k0;
            pa[0] = *(const float4*)(Wp + a_c4);
            pa[1] = *(const float4*)(Wp + 64 * K + a_c4);
            const float* Xp = Xb + (size_t)(k0 + b_row) * N + n0 + b_c4;
            pb[0] = *(const float4*)(Xp);
            pb[1] = *(const float4*)(Xp + 8 * N);
        }

        // compute: 2 k-steps of 8
        #pragma unroll
        for (int ks = 0; ks < 2; ks++) {
            uint32_t af[4][4], bf[4][2];
            #pragma unroll
            for (int mt = 0; mt < 4; mt++) {
                const uint32_t* base = sA + (mwb + mt * 16 + g) * SA_STRIDE + ks * 8 + tg;
                af[mt][0] = base[0];
                af[mt][1] = base[8 * SA_STRIDE];
                af[mt][2] = base[4];
                af[mt][3] = base[8 * SA_STRIDE + 4];
            }
            #pragma unroll
            for (int nt = 0; nt < 4; nt++) {
                const uint32_t* base = sB + (ks * 8 + tg) * SB_STRIDE + nwb + nt * 8 + g;
                bf[nt][0] = base[0];
                bf[nt][1] = base[4 * SB_STRIDE];
            }
            #pragma unroll
            for (int mt = 0; mt < 4; mt++)
                #pragma unroll
                for (int nt = 0; nt < 4; nt++)
                    mma_tf32(acc[mt][nt], af[mt], bf[nt]);
        }
        __syncthreads();
    }

    // Epilogue: fragment c layout: rows g, g+8; cols 2*tg, 2*tg+1 (per tile)
    #pragma unroll
    for (int mt = 0; mt < 4; mt++) {
        int mrow = m0 + mwb + mt * 16 + g;
        float bv0 = bias[mrow];
        float bv1 = bias[mrow + 8];
        float* orow0 = out + ((size_t)b * M + mrow) * N;
        float* orow1 = orow0 + 8 * (size_t)N;
        const float* rrow0 = RES ? res + ((size_t)b * M + mrow) * N : nullptr;
        #pragma unroll
        for (int nt = 0; nt < 4; nt++) {
            int col = n0 + nwb + nt * 8 + 2 * tg;
            float2 o0, o1;
            o0.x = acc[mt][nt][0] + bv0; o0.y = acc[mt][nt][1] + bv0;
            o1.x = acc[mt][nt][2] + bv1; o1.y = acc[mt][nt][3] + bv1;
            if (RES) {
                float2 r0 = *(const float2*)(rrow0 + col);
                float2 r1 = *(const float2*)(rrow0 + 8 * (size_t)N + col);
                o0.x += r0.x; o0.y += r0.y;
                o1.x += r1.x; o1.y += r1.y;
            }
            *(float2*)(orow0 + col) = o0;
            *(float2*)(orow1 + col) = o1;
        }
    }
}

// ---------------------------------------------------------------------------
// Flash attention (fp32 SIMT, unchanged from passing R2)
// ---------------------------------------------------------------------------
#define ATTN_SMEM_FLOATS (4096 + 4096 + 4096 + 64 * 68)
#define ATTN_SMEM_BYTES  (ATTN_SMEM_FLOATS * 4)

__global__ __launch_bounds__(256) void attn_kernel(
    const float* __restrict__ qkv, float* __restrict__ attn_out)
{
    extern __shared__ float sm[];
    float* sQ = sm;
    float* sK = sm + 4096;
    float* sP = sm + 8192;
    float* sV = sm + 12288;

    int hb = blockIdx.y;
    int b = hb >> 3, h = hb & 7;
    int q0 = blockIdx.x * 64;
    const float* base = qkv + ((size_t)b * (3 * CCH) + h * 3 * DH) * TT;
    const float* Qp = base;
    const float* Kp = base + (size_t)DH * TT;
    const float* Vp = base + (size_t)2 * DH * TT;

    int tid = threadIdx.x;
    int tx = tid & 15, ty = tid >> 4;

    for (int i = tid; i < 1024; i += 256) {
        int d = i >> 4, q4 = (i & 15) << 2;
        *(float4*)&sQ[d * 64 + q4] = *(const float4*)(Qp + (size_t)d * TT + q0 + q4);
    }

    float m_run[4], l_run[4], O[4][4];
    #pragma unroll
    for (int i = 0; i < 4; i++) {
        m_run[i] = -INFINITY; l_run[i] = 0.f;
        #pragma unroll
        for (int j = 0; j < 4; j++) O[i][j] = 0.f;
    }

    for (int kt = 0; kt < TT / 64; kt++) {
        int k0 = kt * 64;
        __syncthreads();
        for (int i = tid; i < 1024; i += 256) {
            int d = i >> 4, k4 = (i & 15) << 2;
            *(float4*)&sK[d * 64 + k4] = *(const float4*)(Kp + (size_t)d * TT + k0 + k4);
            *(float4*)&sV[d * 68 + k4] = *(const float4*)(Vp + (size_t)d * TT + k0 + k4);
        }
        __syncthreads();

        float S[4][4] = {};
        #pragma unroll 8
        for (int d = 0; d < 64; d++) {
            float4 a4 = *(const float4*)&sQ[d * 64 + (ty << 2)];
            float4 b4 = *(const float4*)&sK[d * 64 + (tx << 2)];
            float av[4] = {a4.x, a4.y, a4.z, a4.w};
            float bv[4] = {b4.x, b4.y, b4.z, b4.w};
            #pragma unroll
            for (int i = 0; i < 4; i++)
                #pragma unroll
                for (int j = 0; j < 4; j++)
                    S[i][j] += av[i] * bv[j];
        }

        #pragma unroll
        for (int i = 0; i < 4; i++) {
            float mx = fmaxf(fmaxf(S[i][0], S[i][1]), fmaxf(S[i][2], S[i][3])) * 0.125f;
            #pragma unroll
            for (int o = 8; o > 0; o >>= 1)
                mx = fmaxf(mx, __shfl_xor_sync(0xffffffffu, mx, o, 16));
            float mnew = fmaxf(m_run[i], mx);
            float alpha = __expf(m_run[i] - mnew);
            m_run[i] = mnew;
            float rs = 0.f;
            #pragma unroll
            for (int j = 0; j < 4; j++) {
                S[i][j] = __expf(S[i][j] * 0.125f - mnew);
                rs += S[i][j];
            }
            #pragma unroll
            for (int o = 8; o > 0; o >>= 1)
                rs += __shfl_xor_sync(0xffffffffu, rs, o, 16);
            l_run[i] = l_run[i] * alpha + rs;
            #pragma unroll
            for (int j = 0; j < 4; j++) O[i][j] *= alpha;
        }

        #pragma unroll
        for (int i = 0; i < 4; i++)
            *(float4*)&sP[((ty << 2) + i) * 64 + (tx << 2)] =
                make_float4(S[i][0], S[i][1], S[i][2], S[i][3]);
        __syncthreads();

        #pragma unroll 4
        for (int k4 = 0; k4 < 64; k4 += 4) {
            float4 p[4], v[4];
            #pragma unroll
            for (int i = 0; i < 4; i++)
                p[i] = *(const float4*)&sP[((ty << 2) + i) * 64 + k4];
            #pragma unroll
            for (int j = 0; j < 4; j++)
                v[j] = *(const float4*)&sV[((tx << 2) + j) * 68 + k4];
            #pragma unroll
            for (int i = 0; i < 4; i++)
                #pragma unroll
                for (int j = 0; j < 4; j++)
                    O[i][j] += p[i].x * v[j].x + p[i].y * v[j].y
                             + p[i].z * v[j].z + p[i].w * v[j].w;
        }
    }

    float rl[4];
    #pragma unroll
    for (int i = 0; i < 4; i++) rl[i] = 1.f / l_run[i];

    #pragma unroll
    for (int j = 0; j < 4; j++) {
        int d = (tx << 2) + j;
        float4 o4 = make_float4(O[0][j] * rl[0], O[1][j] * rl[1],
                                O[2][j] * rl[2], O[3][j] * rl[3]);
        *(float4*)&attn_out[((size_t)b * CCH + h * DH + d) * TT + q0 + (ty << 2)] = o4;
    }
}

// ---------------------------------------------------------------------------
extern "C" void kernel_launch(void* const* d_in, const int* in_sizes, int n_in,
                              void* d_out, int out_size)
{
    const float* x     = (const float*)d_in[0];
    const float* gsc   = (const float*)d_in[1];
    const float* gbi   = (const float*)d_in[2];
    const float* wqkv  = (const float*)d_in[3];
    const float* bqkv  = (const float*)d_in[4];
    const float* wproj = (const float*)d_in[5];
    const float* bproj = (const float*)d_in[6];
    float* out = (float*)d_out;

    float *xn, *qkv, *attn;
    cudaGetSymbolAddress((void**)&xn,   g_xn);
    cudaGetSymbolAddress((void**)&qkv,  g_qkv);
    cudaGetSymbolAddress((void**)&attn, g_attn);

    cudaFuncSetAttribute(attn_kernel,
                         cudaFuncAttributeMaxDynamicSharedMemorySize,
                         ATTN_SMEM_BYTES);
    cudaFuncSetAttribute(gemm_mma<false>,
                         cudaFuncAttributeMaxDynamicSharedMemorySize,
                         GEMM_SMEM_BYTES);
    cudaFuncSetAttribute(gemm_mma<true>,
                         cudaFuncAttributeMaxDynamicSharedMemorySize,
                         GEMM_SMEM_BYTES);

    gn_kernel<<<BATCH * NGRP, 256>>>(x, gsc, gbi, xn);

    // QKV: M=1536, K=512, N=1024 per batch
    gemm_mma<false><<<dim3(TT / 128, (3 * CCH) / 128, BATCH), 256, GEMM_SMEM_BYTES>>>(
        wqkv, xn, bqkv, nullptr, qkv, 3 * CCH, CCH, TT);

    attn_kernel<<<dim3(TT / 64, BATCH * NHEAD), 256, ATTN_SMEM_BYTES>>>(qkv, attn);

    // Proj + residual: M=512, K=512, N=1024
    gemm_mma<true><<<dim3(TT / 128, CCH / 128, BATCH), 256, GEMM_SMEM_BYTES>>>(
        wproj, attn, bproj, x, out, CCH, CCH, TT);
}

// round 11
// speedup vs baseline: 1.9024x; 1.4042x over previous
#include <cuda_runtime.h>
#include <math.h>
#include <cstdint>

// Problem constants
#define BATCH 16
#define CCH   512
#define TT    1024
#define NHEAD 8
#define DH    64
#define NGRP  32
#define CPG   16

// Scratch (device globals: allocation-free per harness rules)
__device__ float g_xn  [(size_t)BATCH * CCH * TT];        // 32 MB
__device__ float g_qkv [(size_t)BATCH * 3 * CCH * TT];    // 96 MB
__device__ float g_attn[(size_t)BATCH * CCH * TT];        // 32 MB

__device__ __forceinline__ uint32_t f2tf32(float f) {
    uint32_t r;
    asm("cvt.rna.tf32.f32 %0, %1;" : "=r"(r) : "f"(f));
    return r;
}

__device__ __forceinline__ void mma_tf32(
    float d[4], const uint32_t a[4], const uint32_t bfr[2])
{
    asm volatile(
        "mma.sync.aligned.m16n8k8.row.col.f32.tf32.tf32.f32 "
        "{%0,%1,%2,%3}, {%4,%5,%6,%7}, {%8,%9}, {%0,%1,%2,%3};"
        : "+f"(d[0]), "+f"(d[1]), "+f"(d[2]), "+f"(d[3])
        : "r"(a[0]), "r"(a[1]), "r"(a[2]), "r"(a[3]),
          "r"(bfr[0]), "r"(bfr[1]));
}

// ---------------------------------------------------------------------------
// GroupNorm
// ---------------------------------------------------------------------------
__global__ __launch_bounds__(256) void gn_kernel(
    const float* __restrict__ x, const float* __restrict__ sc,
    const float* __restrict__ bi, float* __restrict__ xn)
{
    int b = blockIdx.x >> 5;
    int g = blockIdx.x & 31;
    const float4* xp = (const float4*)(x + ((size_t)b * CCH + g * CPG) * TT);
    float4* op = (float4*)(xn + ((size_t)b * CCH + g * CPG) * TT);
    int tid = threadIdx.x;

    float s = 0.f, s2 = 0.f;
    #pragma unroll 4
    for (int i = tid; i < CPG * TT / 4; i += 256) {
        float4 v = xp[i];
        s  += v.x + v.y + v.z + v.w;
        s2 += v.x * v.x + v.y * v.y + v.z * v.z + v.w * v.w;
    }
    __shared__ float red[512];
    red[tid] = s; red[256 + tid] = s2;
    __syncthreads();
    for (int st = 128; st > 0; st >>= 1) {
        if (tid < st) {
            red[tid] += red[tid + st];
            red[256 + tid] += red[256 + tid + st];
        }
        __syncthreads();
    }
    float mean = red[0] * (1.f / (CPG * TT));
    float var  = red[256] * (1.f / (CPG * TT)) - mean * mean;
    float rinv = rsqrtf(var + 1e-5f);

    #pragma unroll 4
    for (int i = tid; i < CPG * TT / 4; i += 256) {
        int cl = i >> 8;
        float scale = sc[g * CPG + cl] * rinv;
        float bias  = bi[g * CPG + cl];
        float4 v = xp[i];
        float4 o;
        o.x = (v.x - mean) * scale + bias;
        o.y = (v.y - mean) * scale + bias;
        o.z = (v.z - mean) * scale + bias;
        o.w = (v.w - mean) * scale + bias;
        op[i] = o;
    }
}

// ---------------------------------------------------------------------------
// tf32 mma.sync GEMM (validated in R6)
// ---------------------------------------------------------------------------
#define SA_STRIDE 20
#define SB_STRIDE 136
#define SA_FLOATS (128 * SA_STRIDE)
#define SB_FLOATS (16 * SB_STRIDE)
#define GEMM_SMEM_FLOATS (2 * SA_FLOATS + 2 * SB_FLOATS)
#define GEMM_SMEM_BYTES  (GEMM_SMEM_FLOATS * 4)

template <bool RES>
__global__ __launch_bounds__(256, 2) void gemm_mma(
    const float* __restrict__ W, const float* __restrict__ X,
    const float* __restrict__ bias, const float* __restrict__ res,
    float* __restrict__ out, int M, int K, int N)
{
    extern __shared__ uint32_t smem[];

    int b  = blockIdx.z;
    int m0 = blockIdx.y * 128;
    int n0 = blockIdx.x * 128;
    int tid = threadIdx.x;
    int wid = tid >> 5, lane = tid & 31;
    int g = lane >> 2, tg = lane & 3;
    int warp_m = wid & 1, warp_n = wid >> 1;
    int mwb = warp_m * 64;
    int nwb = warp_n * 32;
    const float* Xb = X + (size_t)b * K * N;

    float acc[4][4][4];
    #pragma unroll
    for (int mt = 0; mt < 4; mt++)
        #pragma unroll
        for (int nt = 0; nt < 4; nt++)
            #pragma unroll
            for (int r = 0; r < 4; r++) acc[mt][nt][r] = 0.f;

    int a_row = tid >> 2, a_c4 = (tid & 3) * 4;
    int b_row = tid >> 5, b_c4 = (tid & 31) * 4;

    float4 pa[2], pb[2];
    {
        const float* Wp = W + (size_t)(m0 + a_row) * K;
        pa[0] = *(const float4*)(Wp + a_c4);
        pa[1] = *(const float4*)(Wp + 64 * K + a_c4);
        const float* Xp = Xb + (size_t)b_row * N + n0 + b_c4;
        pb[0] = *(const float4*)(Xp);
        pb[1] = *(const float4*)(Xp + 8 * N);
    }

    const int nchunks = K / 16;
    for (int c = 0; c < nchunks; c++) {
        int buf = c & 1;
        uint32_t* sA = smem + buf * SA_FLOATS;
        uint32_t* sB = smem + 2 * SA_FLOATS + buf * SB_FLOATS;

        {
            uint32_t* p0 = sA + a_row * SA_STRIDE + a_c4;
            p0[0] = f2tf32(pa[0].x); p0[1] = f2tf32(pa[0].y);
            p0[2] = f2tf32(pa[0].z); p0[3] = f2tf32(pa[0].w);
            uint32_t* p1 = sA + (a_row + 64) * SA_STRIDE + a_c4;
            p1[0] = f2tf32(pa[1].x); p1[1] = f2tf32(pa[1].y);
            p1[2] = f2tf32(pa[1].z); p1[3] = f2tf32(pa[1].w);
            uint32_t* q0 = sB + b_row * SB_STRIDE + b_c4;
            q0[0] = f2tf32(pb[0].x); q0[1] = f2tf32(pb[0].y);
            q0[2] = f2tf32(pb[0].z); q0[3] = f2tf32(pb[0].w);
            uint32_t* q1 = sB + (b_row + 8) * SB_STRIDE + b_c4;
            q1[0] = f2tf32(pb[1].x); q1[1] = f2tf32(pb[1].y);
            q1[2] = f2tf32(pb[1].z); q1[3] = f2tf32(pb[1].w);
        }
        __syncthreads();

        if (c + 1 < nchunks) {
            int k0 = (c + 1) * 16;
            const float* Wp = W + (size_t)(m0 + a_row) * K + k0;
            pa[0] = *(const float4*)(Wp + a_c4);
            pa[1] = *(const float4*)(Wp + 64 * K + a_c4);
            const float* Xp = Xb + (size_t)(k0 + b_row) * N + n0 + b_c4;
            pb[0] = *(const float4*)(Xp);
            pb[1] = *(const float4*)(Xp + 8 * N);
        }

        #pragma unroll
        for (int ks = 0; ks < 2; ks++) {
            uint32_t af[4][4], bf[4][2];
            #pragma unroll
            for (int mt = 0; mt < 4; mt++) {
                const uint32_t* base = sA + (mwb + mt * 16 + g) * SA_STRIDE + ks * 8 + tg;
                af[mt][0] = base[0];
                af[mt][1] = base[8 * SA_STRIDE];
                af[mt][2] = base[4];
                af[mt][3] = base[8 * SA_STRIDE + 4];
            }
            #pragma unroll
            for (int nt = 0; nt < 4; nt++) {
                const uint32_t* base = sB + (ks * 8 + tg) * SB_STRIDE + nwb + nt * 8 + g;
                bf[nt][0] = base[0];
                bf[nt][1] = base[4 * SB_STRIDE];
            }
            #pragma unroll
            for (int mt = 0; mt < 4; mt++)
                #pragma unroll
                for (int nt = 0; nt < 4; nt++)
                    mma_tf32(acc[mt][nt], af[mt], bf[nt]);
        }
        __syncthreads();
    }

    #pragma unroll
    for (int mt = 0; mt < 4; mt++) {
        int mrow = m0 + mwb + mt * 16 + g;
        float bv0 = bias[mrow];
        float bv1 = bias[mrow + 8];
        float* orow0 = out + ((size_t)b * M + mrow) * N;
        float* orow1 = orow0 + 8 * (size_t)N;
        const float* rrow0 = RES ? res + ((size_t)b * M + mrow) * N : nullptr;
        #pragma unroll
        for (int nt = 0; nt < 4; nt++) {
            int col = n0 + nwb + nt * 8 + 2 * tg;
            float2 o0, o1;
            o0.x = acc[mt][nt][0] + bv0; o0.y = acc[mt][nt][1] + bv0;
            o1.x = acc[mt][nt][2] + bv1; o1.y = acc[mt][nt][3] + bv1;
            if (RES) {
                float2 r0 = *(const float2*)(rrow0 + col);
                float2 r1 = *(const float2*)(rrow0 + 8 * (size_t)N + col);
                o0.x += r0.x; o0.y += r0.y;
                o1.x += r1.x; o1.y += r1.y;
            }
            *(float2*)(orow0 + col) = o0;
            *(float2*)(orow1 + col) = o1;
        }
    }
}

// ---------------------------------------------------------------------------
// Flash attention on mma.sync tf32.
// CTA: (q-tile of 128) x (head). 8 warps; warp w owns q rows [16w, 16w+16).
// sQ[q][d] (Q^T), sK[s][d] (K^T), sV[d][s] (natural), sP[q][s]. Stride 68.
// ---------------------------------------------------------------------------
#define AST 68
#define ATTN2_SMEM_BYTES (26112 * 4)   // sQ 8704 + sK 4352 + sV 4352 + sP 8704 u32

__global__ __launch_bounds__(256, 2) void attn_mma(
    const float* __restrict__ qkv, float* __restrict__ attn_out)
{
    extern __shared__ uint32_t sm2[];
    uint32_t* sQ = sm2;
    uint32_t* sK = sm2 + 8704;
    uint32_t* sV = sm2 + 13056;
    uint32_t* sP = sm2 + 17408;

    int hb = blockIdx.y;
    int b = hb >> 3, h = hb & 7;
    int q0 = blockIdx.x * 128;
    const float* base = qkv + ((size_t)b * (3 * CCH) + h * 3 * DH) * TT;
    const float* Qp = base;
    const float* Kp = base + (size_t)DH * TT;
    const float* Vp = base + (size_t)2 * DH * TT;

    int tid = threadIdx.x, w = tid >> 5, l = tid & 31;
    int g = l >> 2, tg = l & 3;
    int xorl = (l >> 1) & 3;

    // ---- Q fill: 128q x 64d, transposed, conflict-free XOR'd store order ----
    for (int it = w; it < 64; it += 8) {
        int q4i = (l & 7) | ((it & 3) << 3);        // 0..31
        int d   = (l >> 3) | ((it >> 2) << 2);      // 0..63
        float4 v = *(const float4*)(Qp + (size_t)d * TT + q0 + q4i * 4);
        #pragma unroll
        for (int i = 0; i < 4; i++) {
            int ii = i ^ xorl;
            float val = (ii == 0) ? v.x : (ii == 1) ? v.y : (ii == 2) ? v.z : v.w;
            sQ[(q4i * 4 + ii) * AST + d] = f2tf32(val);
        }
    }

    float m0 = -INFINITY, m1 = -INFINITY, l0 = 0.f, l1 = 0.f;
    float oacc[8][4];
    #pragma unroll
    for (int nt = 0; nt < 8; nt++)
        #pragma unroll
        for (int r = 0; r < 4; r++) oacc[nt][r] = 0.f;

    const uint32_t* qbase = sQ + (16 * w + g) * AST + tg;
    const uint32_t* pbase = sP + (16 * w + g) * AST + tg;
    uint32_t* pst = sP + (16 * w + g) * AST + 2 * tg;

    for (int kt = 0; kt < TT / 64; kt++) {
        int k0 = kt * 64;
        __syncthreads();   // protects sK/sV reuse (and sQ on kt=0)

        // K fill: 64s x 64d transposed
        for (int it = w; it < 32; it += 8) {
            int s4i = (l & 7) | ((it & 1) << 3);    // 0..15
            int d   = (l >> 3) | ((it >> 1) << 2);  // 0..63
            float4 v = *(const float4*)(Kp + (size_t)d * TT + k0 + s4i * 4);
            #pragma unroll
            for (int i = 0; i < 4; i++) {
                int ii = i ^ xorl;
                float val = (ii == 0) ? v.x : (ii == 1) ? v.y : (ii == 2) ? v.z : v.w;
                sK[(s4i * 4 + ii) * AST + d] = f2tf32(val);
            }
        }
        // V fill: natural [d][s]
        for (int idx = tid; idx < 1024; idx += 256) {
            int s4 = idx & 15, d = idx >> 4;
            float4 v = *(const float4*)(Vp + (size_t)d * TT + k0 + s4 * 4);
            uint32_t* p = sV + d * AST + s4 * 4;
            p[0] = f2tf32(v.x); p[1] = f2tf32(v.y);
            p[2] = f2tf32(v.z); p[3] = f2tf32(v.w);
        }
        __syncthreads();

        // ---- S = Q^T K (warp: 16q x 64s, k=d 64) ----
        float sacc[8][4];
        #pragma unroll
        for (int nt = 0; nt < 8; nt++)
            #pragma unroll
            for (int r = 0; r < 4; r++) sacc[nt][r] = 0.f;

        #pragma unroll
        for (int ks = 0; ks < 8; ks++) {
            uint32_t af[4];
            const uint32_t* qb = qbase + ks * 8;
            af[0] = qb[0]; af[1] = qb[8 * AST];
            af[2] = qb[4]; af[3] = qb[8 * AST + 4];
            #pragma unroll
            for (int nt = 0; nt < 8; nt++) {
                uint32_t bf[2];
                const uint32_t* kb = sK + (nt * 8 + g) * AST + ks * 8 + tg;
                bf[0] = kb[0]; bf[1] = kb[4];
                mma_tf32(sacc[nt], af, bf);
            }
        }

        // ---- online softmax (rows r0=16w+g, r1=r0+8; quad shuffles) ----
        float mx0 = sacc[0][0], mx1 = sacc[0][2];
        #pragma unroll
        for (int nt = 0; nt < 8; nt++) {
            mx0 = fmaxf(mx0, fmaxf(sacc[nt][0], sacc[nt][1]));
            mx1 = fmaxf(mx1, fmaxf(sacc[nt][2], sacc[nt][3]));
        }
        mx0 = fmaxf(mx0, __shfl_xor_sync(0xffffffffu, mx0, 1));
        mx0 = fmaxf(mx0, __shfl_xor_sync(0xffffffffu, mx0, 2));
        mx1 = fmaxf(mx1, __shfl_xor_sync(0xffffffffu, mx1, 1));
        mx1 = fmaxf(mx1, __shfl_xor_sync(0xffffffffu, mx1, 2));
        float mn0 = fmaxf(m0, mx0 * 0.125f);
        float mn1 = fmaxf(m1, mx1 * 0.125f);
        float al0 = __expf(m0 - mn0);
        float al1 = __expf(m1 - mn1);
        m0 = mn0; m1 = mn1;

        float rs0 = 0.f, rs1 = 0.f;
        #pragma unroll
        for (int nt = 0; nt < 8; nt++) {
            float p0 = __expf(fmaf(0.125f, sacc[nt][0], -mn0));
            float p1 = __expf(fmaf(0.125f, sacc[nt][1], -mn0));
            float p2 = __expf(fmaf(0.125f, sacc[nt][2], -mn1));
            float p3 = __expf(fmaf(0.125f, sacc[nt][3], -mn1));
            rs0 += p0 + p1; rs1 += p2 + p3;
            pst[nt * 8]           = f2tf32(p0);
            pst[nt * 8 + 1]       = f2tf32(p1);
            pst[nt * 8 + 8 * AST]     = f2tf32(p2);
            pst[nt * 8 + 8 * AST + 1] = f2tf32(p3);
        }
        rs0 += __shfl_xor_sync(0xffffffffu, rs0, 1);
        rs0 += __shfl_xor_sync(0xffffffffu, rs0, 2);
        rs1 += __shfl_xor_sync(0xffffffffu, rs1, 1);
        rs1 += __shfl_xor_sync(0xffffffffu, rs1, 2);
        l0 = l0 * al0 + rs0;
        l1 = l1 * al1 + rs1;
        #pragma unroll
        for (int nt = 0; nt < 8; nt++) {
            oacc[nt][0] *= al0; oacc[nt][1] *= al0;
            oacc[nt][2] *= al1; oacc[nt][3] *= al1;
        }
        __syncwarp();

        // ---- O += P V  (warp: 16q x 64d, k=s 64) ----
        #pragma unroll
        for (int ks = 0; ks < 8; ks++) {
            uint32_t af[4];
            const uint32_t* pb = pbase + ks * 8;
            af[0] = pb[0]; af[1] = pb[8 * AST];
            af[2] = pb[4]; af[3] = pb[8 * AST + 4];
            #pragma unroll
            for (int nt = 0; nt < 8; nt++) {
                uint32_t bf[2];
                const uint32_t* vb = sV + (nt * 8 + g) * AST + ks * 8 + tg;
                bf[0] = vb[0]; bf[1] = vb[4];
                mma_tf32(oacc[nt], af, bf);
            }
        }
    }

    // ---- epilogue: normalize, write attn_out (b, 512, t) ----
    float rl0 = 1.f / l0, rl1 = 1.f / l1;
    int r0 = q0 + 16 * w + g;
    #pragma unroll
    for (int nt = 0; nt < 8; nt++) {
        int d = h * DH + nt * 8 + 2 * tg;
        float* o = attn_out + ((size_t)b * CCH + d) * TT + r0;
        o[0]      = oacc[nt][0] * rl0;
        o[TT]     = oacc[nt][1] * rl0;
        o[8]      = oacc[nt][2] * rl1;
        o[TT + 8] = oacc[nt][3] * rl1;
    }
}

// ---------------------------------------------------------------------------
extern "C" void kernel_launch(void* const* d_in, const int* in_sizes, int n_in,
                              void* d_out, int out_size)
{
    const float* x     = (const float*)d_in[0];
    const float* gsc   = (const float*)d_in[1];
    const float* gbi   = (const float*)d_in[2];
    const float* wqkv  = (const float*)d_in[3];
    const float* bqkv  = (const float*)d_in[4];
    const float* wproj = (const float*)d_in[5];
    const float* bproj = (const float*)d_in[6];
    float* out = (float*)d_out;

    float *xn, *qkv, *attn;
    cudaGetSymbolAddress((void**)&xn,   g_xn);
    cudaGetSymbolAddress((void**)&qkv,  g_qkv);
    cudaGetSymbolAddress((void**)&attn, g_attn);

    cudaFuncSetAttribute(attn_mma,
                         cudaFuncAttributeMaxDynamicSharedMemorySize,
                         ATTN2_SMEM_BYTES);
    cudaFuncSetAttribute(gemm_mma<false>,
                         cudaFuncAttributeMaxDynamicSharedMemorySize,
                         GEMM_SMEM_BYTES);
    cudaFuncSetAttribute(gemm_mma<true>,
                         cudaFuncAttributeMaxDynamicSharedMemorySize,
                         GEMM_SMEM_BYTES);

    gn_kernel<<<BATCH * NGRP, 256>>>(x, gsc, gbi, xn);

    gemm_mma<false><<<dim3(TT / 128, (3 * CCH) / 128, BATCH), 256, GEMM_SMEM_BYTES>>>(
        wqkv, xn, bqkv, nullptr, qkv, 3 * CCH, CCH, TT);

    attn_mma<<<dim3(TT / 128, BATCH * NHEAD), 256, ATTN2_SMEM_BYTES>>>(qkv, attn);

    gemm_mma<true><<<dim3(TT / 128, CCH / 128, BATCH), 256, GEMM_SMEM_BYTES>>>(
        wproj, attn, bproj, x, out, CCH, CCH, TT);
}

// round 13
// speedup vs baseline: 3.3786x; 1.7759x over previous
#include <cuda_runtime.h>
#include <math.h>
#include <cstdint>

// Problem constants
#define BATCH 16
#define CCH   512
#define TT    1024
#define NHEAD 8
#define DH    64
#define NGRP  32
#define CPG   16

// Scratch (device globals: allocation-free per harness rules)
__device__ float g_xn  [(size_t)BATCH * CCH * TT];        // 32 MB (tf32-rounded)
__device__ float g_qkv [(size_t)BATCH * 3 * CCH * TT];    // 96 MB (tf32-rounded)
__device__ float g_attn[(size_t)BATCH * CCH * TT];        // 32 MB (tf32-rounded)
__device__ float g_wq  [(size_t)3 * CCH * CCH];           // 3 MB  (tf32-rounded)
__device__ float g_wp  [(size_t)CCH * CCH];               // 1 MB  (tf32-rounded)

__device__ __forceinline__ uint32_t f2tf32(float f) {
    uint32_t r;
    asm("cvt.rna.tf32.f32 %0, %1;" : "=r"(r) : "f"(f));
    return r;
}

__device__ __forceinline__ void mma_tf32(
    float d[4], const uint32_t a[4], const uint32_t bfr[2])
{
    asm volatile(
        "mma.sync.aligned.m16n8k8.row.col.f32.tf32.tf32.f32 "
        "{%0,%1,%2,%3}, {%4,%5,%6,%7}, {%8,%9}, {%0,%1,%2,%3};"
        : "+f"(d[0]), "+f"(d[1]), "+f"(d[2]), "+f"(d[3])
        : "r"(a[0]), "r"(a[1]), "r"(a[2]), "r"(a[3]),
          "r"(bfr[0]), "r"(bfr[1]));
}

__device__ __forceinline__ uint32_t smem_u32(const void* p) {
    uint32_t a;
    asm("{ .reg .u64 t; cvta.to.shared.u64 t, %1; cvt.u32.u64 %0, t; }"
        : "=r"(a) : "l"(p));
    return a;
}
__device__ __forceinline__ void cp16(uint32_t dst, const void* src) {
    asm volatile("cp.async.ca.shared.global [%0], [%1], 16;"
                 :: "r"(dst), "l"(src) : "memory");
}
#define CP_COMMIT() asm volatile("cp.async.commit_group;" ::: "memory")
template <int N> __device__ __forceinline__ void cp_wait() {
    asm volatile("cp.async.wait_group %0;" :: "n"(N) : "memory");
}

// ---------------------------------------------------------------------------
// Weight tf32 pre-round
// ---------------------------------------------------------------------------
__global__ __launch_bounds__(256) void round_tf32_kernel(
    const float* __restrict__ in, float* __restrict__ out, int n4)
{
    int i = blockIdx.x * 256 + threadIdx.x;
    if (i < n4) {
        float4 v = ((const float4*)in)[i];
        uint4 o;
        o.x = f2tf32(v.x); o.y = f2tf32(v.y);
        o.z = f2tf32(v.z); o.w = f2tf32(v.w);
        ((uint4*)out)[i] = o;
    }
}

// ---------------------------------------------------------------------------
// GroupNorm — output tf32-rounded (consumed only by QKV GEMM)
// ---------------------------------------------------------------------------
__global__ __launch_bounds__(256) void gn_kernel(
    const float* __restrict__ x, const float* __restrict__ sc,
    const float* __restrict__ bi, float* __restrict__ xn)
{
    int b = blockIdx.x >> 5;
    int g = blockIdx.x & 31;
    const float4* xp = (const float4*)(x + ((size_t)b * CCH + g * CPG) * TT);
    float4* op = (float4*)(xn + ((size_t)b * CCH + g * CPG) * TT);
    int tid = threadIdx.x;

    float s = 0.f, s2 = 0.f;
    #pragma unroll 4
    for (int i = tid; i < CPG * TT / 4; i += 256) {
        float4 v = xp[i];
        s  += v.x + v.y + v.z + v.w;
        s2 += v.x * v.x + v.y * v.y + v.z * v.z + v.w * v.w;
    }
    __shared__ float red[512];
    red[tid] = s; red[256 + tid] = s2;
    __syncthreads();
    for (int st = 128; st > 0; st >>= 1) {
        if (tid < st) {
            red[tid] += red[tid + st];
            red[256 + tid] += red[256 + tid + st];
        }
        __syncthreads();
    }
    float mean = red[0] * (1.f / (CPG * TT));
    float var  = red[256] * (1.f / (CPG * TT)) - mean * mean;
    float rinv = rsqrtf(var + 1e-5f);

    #pragma unroll 4
    for (int i = tid; i < CPG * TT / 4; i += 256) {
        int cl = i >> 8;
        float scale = sc[g * CPG + cl] * rinv;
        float bias  = bi[g * CPG + cl];
        float4 v = xp[i];
        float4 o;
        o.x = __uint_as_float(f2tf32((v.x - mean) * scale + bias));
        o.y = __uint_as_float(f2tf32((v.y - mean) * scale + bias));
        o.z = __uint_as_float(f2tf32((v.z - mean) * scale + bias));
        o.w = __uint_as_float(f2tf32((v.w - mean) * scale + bias));
        op[i] = o;
    }
}

// ---------------------------------------------------------------------------
// tf32 mma.sync GEMM, 4-stage cp.async pipeline, 1 sync per K-chunk.
// Inputs W and X must be tf32-pre-rounded. out = W*X + bias (+res).
// ROUND_OUT: round outputs to tf32 (for tensors feeding another mma stage).
// ---------------------------------------------------------------------------
#define SA_STRIDE 20
#define SB_STRIDE 136
#define SA_FLOATS (128 * SA_STRIDE)
#define SB_FLOATS (16 * SB_STRIDE)
#define STAGES 4
#define GEMM_SMEM_BYTES ((STAGES * (SA_FLOATS + SB_FLOATS)) * 4)

template <bool RES, bool ROUND_OUT>
__global__ __launch_bounds__(256, 2) void gemm_mma(
    const float* __restrict__ W, const float* __restrict__ X,
    const float* __restrict__ bias, const float* __restrict__ res,
    float* __restrict__ out, int M, int K, int N)
{
    extern __shared__ uint32_t smem[];
    uint32_t sbase = smem_u32(smem);

    int b  = blockIdx.z;
    int m0 = blockIdx.y * 128;
    int n0 = blockIdx.x * 128;
    int tid = threadIdx.x;
    int wid = tid >> 5, lane = tid & 31;
    int g = lane >> 2, tg = lane & 3;
    int warp_m = wid & 1, warp_n = wid >> 1;
    int mwb = warp_m * 64;
    int nwb = warp_n * 32;
    const float* Xb = X + (size_t)b * K * N;

    float acc[4][4][4];
    #pragma unroll
    for (int mt = 0; mt < 4; mt++)
        #pragma unroll
        for (int nt = 0; nt < 4; nt++)
            #pragma unroll
            for (int r = 0; r < 4; r++) acc[mt][nt][r] = 0.f;

    int a_row = tid >> 2, a_c4 = (tid & 3) * 4;
    int b_row = tid >> 5, b_c4 = (tid & 31) * 4;

    // per-thread cp.async dst byte offsets (within a stage)
    uint32_t dA0 = (a_row * SA_STRIDE + a_c4) * 4;
    uint32_t dA1 = ((a_row + 64) * SA_STRIDE + a_c4) * 4;
    uint32_t dB0 = (b_row * SB_STRIDE + b_c4) * 4;
    uint32_t dB1 = ((b_row + 8) * SB_STRIDE + b_c4) * 4;

    const int nchunks = K / 16;

    auto load_chunk = [&](int c) {
        uint32_t sa = sbase + ((c & (STAGES - 1)) * SA_FLOATS) * 4;
        uint32_t sb = sbase + (STAGES * SA_FLOATS + (c & (STAGES - 1)) * SB_FLOATS) * 4;
        int k0 = c * 16;
        cp16(sa + dA0, W + (size_t)(m0 + a_row) * K + k0 + a_c4);
        cp16(sa + dA1, W + (size_t)(m0 + a_row + 64) * K + k0 + a_c4);
        cp16(sb + dB0, Xb + (size_t)(k0 + b_row) * N + n0 + b_c4);
        cp16(sb + dB1, Xb + (size_t)(k0 + b_row + 8) * N + n0 + b_c4);
    };

    load_chunk(0); CP_COMMIT();
    load_chunk(1); CP_COMMIT();
    load_chunk(2); CP_COMMIT();

    for (int c = 0; c < nchunks; c++) {
        cp_wait<2>();          // group c complete (uniform 1 commit per iter)
        __syncthreads();       // chunk c visible to all; chunk c-1 compute done

        if (c + 3 < nchunks) load_chunk(c + 3);
        CP_COMMIT();

        uint32_t* sA = smem + (c & (STAGES - 1)) * SA_FLOATS;
        uint32_t* sB = smem + STAGES * SA_FLOATS + (c & (STAGES - 1)) * SB_FLOATS;

        #pragma unroll
        for (int ks = 0; ks < 2; ks++) {
            uint32_t af[4][4], bf[4][2];
            #pragma unroll
            for (int mt = 0; mt < 4; mt++) {
                const uint32_t* base = sA + (mwb + mt * 16 + g) * SA_STRIDE + ks * 8 + tg;
                af[mt][0] = base[0];
                af[mt][1] = base[8 * SA_STRIDE];
                af[mt][2] = base[4];
                af[mt][3] = base[8 * SA_STRIDE + 4];
            }
            #pragma unroll
            for (int nt = 0; nt < 4; nt++) {
                const uint32_t* base = sB + (ks * 8 + tg) * SB_STRIDE + nwb + nt * 8 + g;
                bf[nt][0] = base[0];
                bf[nt][1] = base[4 * SB_STRIDE];
            }
            #pragma unroll
            for (int mt = 0; mt < 4; mt++)
                #pragma unroll
                for (int nt = 0; nt < 4; nt++)
                    mma_tf32(acc[mt][nt], af[mt], bf[nt]);
        }
    }

    #pragma unroll
    for (int mt = 0; mt < 4; mt++) {
        int mrow = m0 + mwb + mt * 16 + g;
        float bv0 = bias[mrow];
        float bv1 = bias[mrow + 8];
        float* orow0 = out + ((size_t)b * M + mrow) * N;
        float* orow1 = orow0 + 8 * (size_t)N;
        const float* rrow0 = RES ? res + ((size_t)b * M + mrow) * N : nullptr;
        #pragma unroll
        for (int nt = 0; nt < 4; nt++) {
            int col = n0 + nwb + nt * 8 + 2 * tg;
            float2 o0, o1;
            o0.x = acc[mt][nt][0] + bv0; o0.y = acc[mt][nt][1] + bv0;
            o1.x = acc[mt][nt][2] + bv1; o1.y = acc[mt][nt][3] + bv1;
            if (RES) {
                float2 r0 = *(const float2*)(rrow0 + col);
                float2 r1 = *(const float2*)(rrow0 + 8 * (size_t)N + col);
                o0.x += r0.x; o0.y += r0.y;
                o1.x += r1.x; o1.y += r1.y;
            }
            if (ROUND_OUT) {
                o0.x = __uint_as_float(f2tf32(o0.x));
                o0.y = __uint_as_float(f2tf32(o0.y));
                o1.x = __uint_as_float(f2tf32(o1.x));
                o1.y = __uint_as_float(f2tf32(o1.y));
            }
            *(float2*)(orow0 + col) = o0;
            *(float2*)(orow1 + col) = o1;
        }
    }
}

// ---------------------------------------------------------------------------
// Flash attention on mma.sync tf32. qkv is tf32-pre-rounded.
// CTA: (q-tile of 128) x (head). 8 warps; warp w owns q rows [16w, 16w+16).
// sQ[q][d] (Q^T), sK[s][d] (K^T), sV[d][s] (natural, cp.async), sP[q][s].
// ---------------------------------------------------------------------------
#define AST 68
#define ATTN2_SMEM_BYTES (26112 * 4)
#define L2E 1.4426950408889634f
#define SC2 (0.125f * L2E)     // softmax scale folded into log2-domain

__global__ __launch_bounds__(256, 2) void attn_mma(
    const float* __restrict__ qkv, float* __restrict__ attn_out)
{
    extern __shared__ uint32_t sm2[];
    uint32_t* sQ = sm2;
    uint32_t* sK = sm2 + 8704;
    uint32_t* sV = sm2 + 13056;
    uint32_t* sP = sm2 + 17408;
    uint32_t sVb = smem_u32(sV);

    int hb = blockIdx.y;
    int b = hb >> 3, h = hb & 7;
    int q0 = blockIdx.x * 128;
    const float* base = qkv + ((size_t)b * (3 * CCH) + h * 3 * DH) * TT;
    const float* Qp = base;
    const float* Kp = base + (size_t)DH * TT;
    const float* Vp = base + (size_t)2 * DH * TT;

    int tid = threadIdx.x, w = tid >> 5, l = tid & 31;
    int g = l >> 2, tg = l & 3;
    int xorl = (l >> 1) & 3;

    // ---- Q fill: 128q x 64d, transposed, conflict-free XOR'd store order ----
    for (int it = w; it < 64; it += 8) {
        int q4i = (l & 7) | ((it & 3) << 3);
        int d   = (l >> 3) | ((it >> 2) << 2);
        float4 v = *(const float4*)(Qp + (size_t)d * TT + q0 + q4i * 4);
        #pragma unroll
        for (int i = 0; i < 4; i++) {
            int ii = i ^ xorl;
            float val = (ii == 0) ? v.x : (ii == 1) ? v.y : (ii == 2) ? v.z : v.w;
            sQ[(q4i * 4 + ii) * AST + d] = __float_as_uint(val);
        }
    }

    float m0 = -INFINITY, m1 = -INFINITY, l0 = 0.f, l1 = 0.f;
    float oacc[8][4];
    #pragma unroll
    for (int nt = 0; nt < 8; nt++)
        #pragma unroll
        for (int r = 0; r < 4; r++) oacc[nt][r] = 0.f;

    const uint32_t* qbase = sQ + (16 * w + g) * AST + tg;
    const uint32_t* pbase = sP + (16 * w + g) * AST + tg;
    uint32_t* pst = sP + (16 * w + g) * AST + 2 * tg;

    // per-thread V cp.async indices: 4 chunks of 16B
    int v_s4 = tid & 15, v_d0 = tid >> 4;   // d0 + {0,16,32,48}

    for (int kt = 0; kt < TT / 64; kt++) {
        int k0 = kt * 64;
        __syncthreads();   // protects sK/sV reuse (and sQ on kt=0)

        // V fill via cp.async (overlaps with K transpose below)
        #pragma unroll
        for (int j = 0; j < 4; j++) {
            int d = v_d0 + j * 16;
            cp16(sVb + (d * AST + v_s4 * 4) * 4,
                 Vp + (size_t)d * TT + k0 + v_s4 * 4);
        }
        CP_COMMIT();

        // K fill: 64s x 64d transposed
        for (int it = w; it < 32; it += 8) {
            int s4i = (l & 7) | ((it & 1) << 3);
            int d   = (l >> 3) | ((it >> 1) << 2);
            float4 v = *(const float4*)(Kp + (size_t)d * TT + k0 + s4i * 4);
            #pragma unroll
            for (int i = 0; i < 4; i++) {
                int ii = i ^ xorl;
                float val = (ii == 0) ? v.x : (ii == 1) ? v.y : (ii == 2) ? v.z : v.w;
                sK[(s4i * 4 + ii) * AST + d] = __float_as_uint(val);
            }
        }
        cp_wait<0>();
        __syncthreads();

        // ---- S = Q^T K (warp: 16q x 64s, k=d 64) ----
        float sacc[8][4];
        #pragma unroll
        for (int nt = 0; nt < 8; nt++)
            #pragma unroll
            for (int r = 0; r < 4; r++) sacc[nt][r] = 0.f;

        #pragma unroll
        for (int ks = 0; ks < 8; ks++) {
            uint32_t af[4];
            const uint32_t* qb = qbase + ks * 8;
            af[0] = qb[0]; af[1] = qb[8 * AST];
            af[2] = qb[4]; af[3] = qb[8 * AST + 4];
            #pragma unroll
            for (int nt = 0; nt < 8; nt++) {
                uint32_t bf[2];
                const uint32_t* kb = sK + (nt * 8 + g) * AST + ks * 8 + tg;
                bf[0] = kb[0]; bf[1] = kb[4];
                mma_tf32(sacc[nt], af, bf);
            }
        }

        // ---- online softmax in log2 domain (rows 16w+g, +8) ----
        float mx0 = sacc[0][0], mx1 = sacc[0][2];
        #pragma unroll
        for (int nt = 0; nt < 8; nt++) {
            mx0 = fmaxf(mx0, fmaxf(sacc[nt][0], sacc[nt][1]));
            mx1 = fmaxf(mx1, fmaxf(sacc[nt][2], sacc[nt][3]));
        }
        mx0 = fmaxf(mx0, __shfl_xor_sync(0xffffffffu, mx0, 1));
        mx0 = fmaxf(mx0, __shfl_xor_sync(0xffffffffu, mx0, 2));
        mx1 = fmaxf(mx1, __shfl_xor_sync(0xffffffffu, mx1, 1));
        mx1 = fmaxf(mx1, __shfl_xor_sync(0xffffffffu, mx1, 2));
        float mn0 = fmaxf(m0, mx0 * SC2);
        float mn1 = fmaxf(m1, mx1 * SC2);
        float al0 = exp2f(m0 - mn0);
        float al1 = exp2f(m1 - mn1);
        m0 = mn0; m1 = mn1;

        float rs0 = 0.f, rs1 = 0.f;
        #pragma unroll
        for (int nt = 0; nt < 8; nt++) {
            float p0 = exp2f(fmaf(SC2, sacc[nt][0], -mn0));
            float p1 = exp2f(fmaf(SC2, sacc[nt][1], -mn0));
            float p2 = exp2f(fmaf(SC2, sacc[nt][2], -mn1));
            float p3 = exp2f(fmaf(SC2, sacc[nt][3], -mn1));
            rs0 += p0 + p1; rs1 += p2 + p3;
            pst[nt * 8]               = f2tf32(p0);
            pst[nt * 8 + 1]           = f2tf32(p1);
            pst[nt * 8 + 8 * AST]     = f2tf32(p2);
            pst[nt * 8 + 8 * AST + 1] = f2tf32(p3);
        }
        rs0 += __shfl_xor_sync(0xffffffffu, rs0, 1);
        rs0 += __shfl_xor_sync(0xffffffffu, rs0, 2);
        rs1 += __shfl_xor_sync(0xffffffffu, rs1, 1);
        rs1 += __shfl_xor_sync(0xffffffffu, rs1, 2);
        l0 = l0 * al0 + rs0;
        l1 = l1 * al1 + rs1;
        #pragma unroll
        for (int nt = 0; nt < 8; nt++) {
            oacc[nt][0] *= al0; oacc[nt][1] *= al0;
            oacc[nt][2] *= al1; oacc[nt][3] *= al1;
        }
        __syncwarp();

        // ---- O += P V  (warp: 16q x 64d, k=s 64) ----
        #pragma unroll
        for (int ks = 0; ks < 8; ks++) {
            uint32_t af[4];
            const uint32_t* pb = pbase + ks * 8;
            af[0] = pb[0]; af[1] = pb[8 * AST];
            af[2] = pb[4]; af[3] = pb[8 * AST + 4];
            #pragma unroll
            for (int nt = 0; nt < 8; nt++) {
                uint32_t bf[2];
                const uint32_t* vb = sV + (nt * 8 + g) * AST + ks * 8 + tg;
                bf[0] = vb[0]; bf[1] = vb[4];
                mma_tf32(oacc[nt], af, bf);
            }
        }
    }

    // ---- epilogue: normalize, tf32-round, write attn_out (b, 512, t) ----
    float rl0 = 1.f / l0, rl1 = 1.f / l1;
    int r0 = q0 + 16 * w + g;
    #pragma unroll
    for (int nt = 0; nt < 8; nt++) {
        int d = h * DH + nt * 8 + 2 * tg;
        float* o = attn_out + ((size_t)b * CCH + d) * TT + r0;
        o[0]      = __uint_as_float(f2tf32(oacc[nt][0] * rl0));
        o[TT]     = __uint_as_float(f2tf32(oacc[nt][1] * rl0));
        o[8]      = __uint_as_float(f2tf32(oacc[nt][2] * rl1));
        o[TT + 8] = __uint_as_float(f2tf32(oacc[nt][3] * rl1));
    }
}

// ---------------------------------------------------------------------------
extern "C" void kernel_launch(void* const* d_in, const int* in_sizes, int n_in,
                              void* d_out, int out_size)
{
    const float* x     = (const float*)d_in[0];
    const float* gsc   = (const float*)d_in[1];
    const float* gbi   = (const float*)d_in[2];
    const float* wqkv  = (const float*)d_in[3];
    const float* bqkv  = (const float*)d_in[4];
    const float* wproj = (const float*)d_in[5];
    const float* bproj = (const float*)d_in[6];
    float* out = (float*)d_out;

    float *xn, *qkv, *attn, *wq, *wp;
    cudaGetSymbolAddress((void**)&xn,   g_xn);
    cudaGetSymbolAddress((void**)&qkv,  g_qkv);
    cudaGetSymbolAddress((void**)&attn, g_attn);
    cudaGetSymbolAddress((void**)&wq,   g_wq);
    cudaGetSymbolAddress((void**)&wp,   g_wp);

    cudaFuncSetAttribute(attn_mma,
                         cudaFuncAttributeMaxDynamicSharedMemorySize,
                         ATTN2_SMEM_BYTES);
    cudaFuncSetAttribute(gemm_mma<false, true>,
                         cudaFuncAttributeMaxDynamicSharedMemorySize,
                         GEMM_SMEM_BYTES);
    cudaFuncSetAttribute(gemm_mma<true, false>,
                         cudaFuncAttributeMaxDynamicSharedMemorySize,
                         GEMM_SMEM_BYTES);

    // Pre-round weights (independent of GN; runs concurrently in-order stream)
    round_tf32_kernel<<<(3 * CCH * CCH / 4 + 255) / 256, 256>>>(
        wqkv, wq, 3 * CCH * CCH / 4);
    round_tf32_kernel<<<(CCH * CCH / 4 + 255) / 256, 256>>>(
        wproj, wp, CCH * CCH / 4);

    gn_kernel<<<BATCH * NGRP, 256>>>(x, gsc, gbi, xn);

    gemm_mma<false, true><<<dim3(TT / 128, (3 * CCH) / 128, BATCH), 256, GEMM_SMEM_BYTES>>>(
        wq, xn, bqkv, nullptr, qkv, 3 * CCH, CCH, TT);

    attn_mma<<<dim3(TT / 128, BATCH * NHEAD), 256, ATTN2_SMEM_BYTES>>>(qkv, attn);

    gemm_mma<true, false><<<dim3(TT / 128, CCH / 128, BATCH), 256, GEMM_SMEM_BYTES>>>(
        wp, attn, bproj, x, out, CCH, CCH, TT);
}